// round 12
// baseline (speedup 1.0000x reference)
#include <cuda_runtime.h>
#include <cuda_fp16.h>
#include <cstdint>

#define B_TOK 4096
#define D_INV 2048
#define NF    16384
#define TOPK  32
#define KAUX  256
#define DEADTH 100

// GEMM tiling
#define TM 128
#define TN 128
#define BK 64
#define NIT (D_INV / BK)          // 32
#define STAGE_U32 8192
#define GEMM_SMEM (3 * STAGE_U32 * 4)   // 98304 bytes, 3 stages

#define CAND_MAX 256
#define WD8_SCALE 128.0f
#define WD8_INV   0.0078125f

// ---------------- scratch (device globals; no allocation allowed) ----------
__device__ __half   g_pre[(size_t)B_TOK * NF];
__device__ uint32_t g_A16u[(size_t)B_TOK * D_INV / 2];
__device__ uint32_t g_B16u[(size_t)NF * D_INV / 2];
__device__ uint32_t g_Wd16u[(size_t)NF * D_INV / 2];
__device__ unsigned short g_Wd8u[(size_t)NF * D_INV / 2];
__device__ int    g_tk_idx[B_TOK * TOPK];
__device__ float  g_tk_val[B_TOK * TOPK];
__device__ int    g_tk_cnt[B_TOK];
__device__ int    g_ax_idx[B_TOK * KAUX];
__device__ float  g_ax_val[B_TOK * KAUX];
__device__ int    g_ax_cnt[B_TOK];
__device__ int    g_active[NF];
__device__ unsigned g_deadbits[NF / 32];
__device__ double g_pmse[B_TOK];
__device__ double g_paux[B_TOK];

// ---------------- helpers ----------------------------------------------------
__device__ __forceinline__ uint32_t smem_u32(const void* p) {
    uint32_t a;
    asm("{ .reg .u64 t; cvta.to.shared.u64 t, %1; cvt.u32.u64 %0, t; }"
        : "=r"(a) : "l"(p));
    return a;
}
__device__ __forceinline__ void cpa16(uint32_t dst, const void* src) {
    asm volatile("cp.async.cg.shared.global [%0], [%1], 16;" :: "r"(dst), "l"(src));
}
__device__ __forceinline__ uint32_t pkh(__half a, __half b) {
    __half2 t = __halves2half2(a, b);
    return *reinterpret_cast<uint32_t*>(&t);
}
__device__ __forceinline__ float2 uph(uint32_t u) {
    __half2 t = *reinterpret_cast<__half2*>(&u);
    return __half22float2(t);
}
__device__ __forceinline__ unsigned short mapk16(unsigned short h) {
    return (h & 0x8000u) ? (unsigned short)(~h) : (unsigned short)(h | 0x8000u);
}
__device__ __forceinline__ float val16(unsigned u) {
    unsigned short b = (u & 0x8000u) ? (unsigned short)(u ^ 0x8000u)
                                     : (unsigned short)(~u & 0xFFFFu);
    return __half2float(__ushort_as_half(b));
}

#define MMA_F16(C, A, B) \
    asm volatile("mma.sync.aligned.m16n8k16.row.col.f32.f16.f16.f32 " \
        "{%0,%1,%2,%3}, {%4,%5,%6,%7}, {%8,%9}, {%0,%1,%2,%3};" \
        : "+f"((C)[0]), "+f"((C)[1]), "+f"((C)[2]), "+f"((C)[3]) \
        : "r"((A)[0]), "r"((A)[1]), "r"((A)[2]), "r"((A)[3]), \
          "r"((B)[0]), "r"((B)[1]))

#define LDSM4(R0, R1, R2, R3, ADDR) \
    asm volatile("ldmatrix.sync.aligned.m8n8.x4.shared.b16 {%0,%1,%2,%3}, [%4];" \
        : "=r"(R0), "=r"(R1), "=r"(R2), "=r"(R3) : "r"(ADDR))

// ---------------- convert pre-pass -------------------------------------------
__global__ __launch_bounds__(256) void conv_a_kernel(const float* __restrict__ A) {
    size_t i = (size_t)blockIdx.x * 256 + threadIdx.x;
    const float4 v = ((const float4*)A)[i];
    ((uint2*)g_A16u)[i] = make_uint2(
        pkh(__float2half_rn(v.x), __float2half_rn(v.y)),
        pkh(__float2half_rn(v.z), __float2half_rn(v.w)));
}

__global__ __launch_bounds__(256) void conv_wd_kernel(const float* __restrict__ Wd) {
    size_t i = (size_t)blockIdx.x * 256 + threadIdx.x;
    const float4 v = ((const float4*)Wd)[i];
    ((uint2*)g_Wd16u)[i] = make_uint2(
        pkh(__float2half_rn(v.x), __float2half_rn(v.y)),
        pkh(__float2half_rn(v.z), __float2half_rn(v.w)));
    unsigned short lo, hi;
    asm("cvt.rn.satfinite.e4m3x2.f32 %0, %1, %2;"
        : "=h"(lo) : "f"(v.y * WD8_SCALE), "f"(v.x * WD8_SCALE));
    asm("cvt.rn.satfinite.e4m3x2.f32 %0, %1, %2;"
        : "=h"(hi) : "f"(v.w * WD8_SCALE), "f"(v.z * WD8_SCALE));
    ((uint32_t*)g_Wd8u)[i] = (uint32_t)lo | ((uint32_t)hi << 16);
}

__global__ __launch_bounds__(256) void conv_b_kernel(const float* __restrict__ B) {
    __shared__ float sh[32][33];
    const int n0 = blockIdx.x * 32;
    const int k0 = blockIdx.y * 32;
    const int tx = threadIdx.x & 31, ty = threadIdx.x >> 5;
    if (blockIdx.y == 0 && threadIdx.x < 32) g_active[n0 + threadIdx.x] = 0;
#pragma unroll
    for (int q = 0; q < 4; q++) {
        int k = ty + q * 8;
        sh[k][tx] = B[(size_t)(k0 + k) * NF + n0 + tx];
    }
    __syncthreads();
#pragma unroll
    for (int q = 0; q < 2; q++) {
        int idx = threadIdx.x + q * 256;
        int n = idx & 31, kp = idx >> 5;
        float v0 = sh[kp * 2][n], v1 = sh[kp * 2 + 1][n];
        size_t o = (size_t)(n0 + n) * (D_INV / 2) + (k0 >> 1) + kp;
        g_B16u[o] = pkh(__float2half_rn(v0), __float2half_rn(v1));
    }
}

// ---------------- single-term fp16 mma.sync GEMM ----------------------------
__global__ __launch_bounds__(256, 2)
void gemm_f16_kernel(const float* __restrict__ bias) {
    extern __shared__ uint32_t smw[];
    const int tid = threadIdx.x;
    const int w = tid >> 5, lane = tid & 31;
    const int m0 = blockIdx.x * TM;
    const int n0 = blockIdx.y * TN;
    const int wm = (w & 3) * 32;
    const int wn = (w >> 2) * 64;
    const int lr = lane >> 2, lc = lane & 3;
    const uint32_t smbase = smem_u32(smw);

    float c[2][8][4];
#pragma unroll
    for (int mi = 0; mi < 2; mi++)
#pragma unroll
        for (int ni = 0; ni < 8; ni++)
#pragma unroll
            for (int j = 0; j < 4; j++) c[mi][ni][j] = 0.f;

    auto loadStage = [&](int s, int kt) {
        uint32_t* st = smw + s * STAGE_U32;
        const int ktu = kt >> 1;
#pragma unroll
        for (int q = 0; q < 8; q++) {
            int t = tid + q * 256;
            int pl = t >> 10;
            int rem = t & 1023;
            int row = rem >> 3, ch = rem & 7;
            const uint32_t* base = pl ? g_B16u : g_A16u;
            const uint32_t* src = base +
                (size_t)((pl ? n0 : m0) + row) * (D_INV / 2) + ktu + ch * 4;
            uint32_t* dst = st + pl * 4096 + row * 32 + ((ch ^ (row & 7)) << 2);
            cpa16(smem_u32(dst), src);
        }
    };

    loadStage(0, 0);
    asm volatile("cp.async.commit_group;");
    loadStage(1, BK);
    asm volatile("cp.async.commit_group;");

    const int a_rowadd = ((lane >> 3) & 1) * 8 + (lane & 7);
    const int a_chadd  = lane >> 4;
    const int b_rowadd = (lane >> 4) * 8 + (lane & 7);
    const int b_chadd  = (lane >> 3) & 1;

    int s_cur = 0, s_nxt = 2;
    for (int i = 0; i < NIT; i++) {
        asm volatile("cp.async.wait_group 1;" ::: "memory");
        __syncthreads();

        const uint32_t sb = smbase + s_cur * (STAGE_U32 * 4);

#pragma unroll
        for (int ks = 0; ks < 4; ks++) {
            const int c0 = 2 * ks;
            uint32_t aa[2][4], bb[8][2];
#pragma unroll
            for (int mi = 0; mi < 2; mi++) {
                int R = wm + mi * 16 + a_rowadd;
                int ch = c0 + a_chadd;
                uint32_t off = (uint32_t)(R * 32 + ((ch ^ (R & 7)) << 2)) * 4;
                LDSM4(aa[mi][0], aa[mi][1], aa[mi][2], aa[mi][3], sb + off);
            }
#pragma unroll
            for (int nip = 0; nip < 4; nip++) {
                int N = wn + nip * 16 + b_rowadd;
                int ch = c0 + b_chadd;
                uint32_t off = (uint32_t)(N * 32 + ((ch ^ (N & 7)) << 2)) * 4;
                LDSM4(bb[2 * nip][0], bb[2 * nip][1],
                      bb[2 * nip + 1][0], bb[2 * nip + 1][1], sb + 16384 + off);
            }
#pragma unroll
            for (int mi = 0; mi < 2; mi++)
#pragma unroll
                for (int ni = 0; ni < 8; ni++)
                    MMA_F16(c[mi][ni], aa[mi], bb[ni]);
        }
        if (i + 2 < NIT) loadStage(s_nxt, (i + 2) * BK);
        asm volatile("cp.async.commit_group;");
        s_cur = (s_cur == 2) ? 0 : s_cur + 1;
        s_nxt = (s_nxt == 2) ? 0 : s_nxt + 1;
    }

#pragma unroll
    for (int mi = 0; mi < 2; mi++) {
        int row = m0 + wm + mi * 16 + lr;
#pragma unroll
        for (int ni = 0; ni < 8; ni++) {
            int col = n0 + wn + ni * 8 + lc * 2;
            float2 bv = *(const float2*)(bias + col);
            uint32_t p0 = pkh(__float2half_rn(c[mi][ni][0] + bv.x),
                              __float2half_rn(c[mi][ni][1] + bv.y));
            uint32_t p1 = pkh(__float2half_rn(c[mi][ni][2] + bv.x),
                              __float2half_rn(c[mi][ni][3] + bv.y));
            *(uint32_t*)(g_pre + (size_t)row * NF + col) = p0;
            *(uint32_t*)(g_pre + (size_t)(row + 8) * NF + col) = p1;
        }
    }
}

// ---------------- dead mask (bitmask via ballot) -----------------------------
__global__ void dead_kernel(const long long* __restrict__ steps) {
    int f = blockIdx.x * blockDim.x + threadIdx.x;
    bool dead = false;
    if (f < NF)
        dead = (g_active[f] == 0 && (steps[f] + 1) >= (long long)DEADTH);
    unsigned m = __ballot_sync(0xFFFFFFFFu, dead);
    if ((threadIdx.x & 31) == 0 && f < NF) g_deadbits[f >> 5] = m;
}

// ---------------- per-row top-k: fused-build 2-pass radix --------------------
__global__ __launch_bounds__(256)
void topk_kernel(int k, int is_aux, float* __restrict__ coeffs_out,
                 const float* __restrict__ xin, const float* __restrict__ Wenc,
                 const float* __restrict__ be) {
    extern __shared__ char shm_raw[];
    double*   redd     = (double*)shm_raw;                 // 256
    unsigned* hist     = (unsigned*)(redd + 256);          // 256
    unsigned* wsum     = hist + 256;                       // 256
    int*      cand_idx = (int*)(wsum + 256);               // 256
    unsigned* cand_key = (unsigned*)(cand_idx + 256);      // 256
    float*    exv      = (float*)(cand_key + 256);         // 256
    unsigned* sdead    = (unsigned*)(exv + 256);           // 512
    unsigned short* keys = (unsigned short*)(sdead + 512); // NF
    __shared__ int s_bin, s_rem, s_cnt, s_pos, s_nhi, s_nc;

    const int r = blockIdx.x;
    const int tid = threadIdx.x;
    const int lane = tid & 31, wid = tid >> 5;
    const __half* row = g_pre + (size_t)r * NF;
    uint32_t* keys32 = (uint32_t*)keys;

    if (is_aux)
        for (int i = tid; i < NF / 32; i += 256) sdead[i] = g_deadbits[i];
    hist[tid] = 0;
    __syncthreads();

    // fused: build keys + high-byte histogram
    for (int i = tid; i < NF / 2; i += 256) {
        uint32_t pair = ((const uint32_t*)row)[i];
        unsigned short k0 = mapk16((unsigned short)(pair & 0xFFFFu));
        unsigned short k1 = mapk16((unsigned short)(pair >> 16));
        if (is_aux) {
            unsigned db = sdead[i >> 4];
            if (!((db >> ((2 * i) & 31)) & 1u))     k0 = 0;
            if (!((db >> ((2 * i + 1) & 31)) & 1u)) k1 = 0;
        }
        keys32[i] = (uint32_t)k0 | ((uint32_t)k1 << 16);
        atomicAdd(&hist[k0 >> 8], 1u);
        atomicAdd(&hist[k1 >> 8], 1u);
    }
    __syncthreads();

    // suffix-scan helper (warp shuffle)
    auto suffix_select = [&](int remaining) {
        unsigned v = hist[tid];
        unsigned myh = v;
#pragma unroll
        for (int d = 1; d < 32; d <<= 1) {
            unsigned t = __shfl_down_sync(0xFFFFFFFFu, v, d);
            if (lane + d < 32) v += t;
        }
        if (lane == 0) wsum[wid] = v;
        __syncthreads();
        if (tid < 8) {
            unsigned wv = wsum[tid];
#pragma unroll
            for (int d = 1; d < 8; d <<= 1) {
                unsigned t = __shfl_down_sync(0xFFu, wv, d, 8);
                if (tid + d < 8) wv += t;
            }
            wsum[tid] = wv;
        }
        __syncthreads();
        unsigned suffix = v + ((wid < 7) ? wsum[wid + 1] : 0u);
        unsigned suffix_excl = suffix - myh;
        if ((int)suffix >= remaining && (int)suffix_excl < remaining) {
            s_bin = tid;
            s_rem = remaining - (int)suffix_excl;
        }
        __syncthreads();
    };

    suffix_select(k);
    const unsigned bin1 = (unsigned)s_bin;
    int remaining = s_rem;
    __syncthreads();

    // pass 2: low byte among keys whose high byte == bin1 (vectorized)
    hist[tid] = 0;
    __syncthreads();
    for (int i = tid; i < NF / 2; i += 256) {
        uint32_t pr = keys32[i];
        unsigned k0 = pr & 0xFFFFu, k1 = pr >> 16;
        if ((k0 >> 8) == bin1) atomicAdd(&hist[k0 & 255u], 1u);
        if ((k1 >> 8) == bin1) atomicAdd(&hist[k1 & 255u], 1u);
    }
    __syncthreads();
    suffix_select(remaining);
    const unsigned thr = (bin1 << 8) | (unsigned)s_bin;

    if (tid == 0) { s_cnt = 0; s_pos = 0; s_nhi = 0; s_nc = 0; }
    __syncthreads();

    if (!is_aux) {
        const float DELTA = 3e-3f;
        const float v32 = val16(thr);
        const float vhi = v32 + DELTA, vlo = v32 - DELTA;
        const unsigned khiK = (unsigned)mapk16(
            (unsigned short)__half_as_ushort(__float2half_rn(vhi)));

        auto classify = [&](unsigned u, int i) {
            float v = val16(u);
            if (v > vhi) {
                atomicAdd(&s_nhi, 1);
                if (v > 0.f) {
                    int p = atomicAdd(&s_pos, 1);
                    g_tk_idx[r * TOPK + p] = i;
                    g_tk_val[r * TOPK + p] = v;
                    coeffs_out[(size_t)r * NF + i] = v;
                    g_active[i] = 1;
                }
            } else if (v >= vlo) {
                int p = atomicAdd(&s_nc, 1);
                if (p < CAND_MAX) { cand_idx[p] = i; cand_key[p] = u; }
            }
        };
        for (int i = tid; i < NF / 2; i += 256) {
            uint32_t pr = keys32[i];
            unsigned k0 = pr & 0xFFFFu, k1 = pr >> 16;
            // cheap prefilter: anything far below threshold key skips float math
            if (k0 + 2048 >= thr) classify(k0, 2 * i);
            if (k1 + 2048 >= thr) classify(k1, 2 * i + 1);
        }
        __syncthreads();

        const int need = TOPK - s_nhi;
        const int nc = (s_nc < CAND_MAX) ? s_nc : CAND_MAX;

        auto sel_write = [&](int i, float v) {
            if (v > 0.f) {
                int p = atomicAdd(&s_pos, 1);
                g_tk_idx[r * TOPK + p] = i;
                g_tk_val[r * TOPK + p] = v;
                coeffs_out[(size_t)r * NF + i] = v;
                g_active[i] = 1;
            }
        };

        if (nc == need) {
            if (tid < nc) sel_write(cand_idx[tid], val16(cand_key[tid]));
        } else {
            const float* xr = xin + (size_t)r * D_INV;
            for (int t = 0; t < nc; t++) {
                const float* Wc = Wenc + cand_idx[t];
                double part = 0.0;
#pragma unroll
                for (int q = 0; q < 8; q++) {
                    int p = tid + q * 256;
                    part += (double)xr[p] * (double)Wc[(size_t)p * NF];
                }
                redd[tid] = part; __syncthreads();
                for (int s = 128; s > 0; s >>= 1) {
                    if (tid < s) redd[tid] += redd[tid + s];
                    __syncthreads();
                }
                if (tid == 0) exv[t] = (float)(redd[0] + (double)be[cand_idx[t]]);
                __syncthreads();
            }
            if (tid < nc) {
                float mv = exv[tid];
                int mi = cand_idx[tid];
                int rank = 0;
                for (int u = 0; u < nc; u++) {
                    if (exv[u] > mv || (exv[u] == mv && cand_idx[u] < mi)) rank++;
                }
                if (rank < need) sel_write(mi, mv);
            }
        }
        __syncthreads();
        if (tid == 0) g_tk_cnt[r] = s_pos;
    } else {
        auto take = [&](unsigned u, int i) {
            if (u > thr) {
                atomicAdd(&s_cnt, 1);
                float v = val16(u);
                if (v > 0.f) {
                    int p = atomicAdd(&s_pos, 1);
                    if (p < KAUX) {
                        g_ax_idx[r * KAUX + p] = i;
                        g_ax_val[r * KAUX + p] = v;
                    }
                }
            }
        };
        for (int i = tid; i < NF / 2; i += 256) {
            uint32_t pr = keys32[i];
            unsigned k0 = pr & 0xFFFFu, k1 = pr >> 16;
            if (k0 > thr) take(k0, 2 * i);
            if (k1 > thr) take(k1, 2 * i + 1);
        }
        __syncthreads();

        const int need = k - s_cnt;
        if (need > 0 && thr != 0u) {
            for (int i = tid; i < NF / 2; i += 256) {
                uint32_t pr = keys32[i];
                if ((pr & 0xFFFFu) == thr) {
                    int p = atomicAdd(&s_nc, 1);
                    if (p < CAND_MAX) cand_idx[p] = 2 * i;
                }
                if ((pr >> 16) == thr) {
                    int p = atomicAdd(&s_nc, 1);
                    if (p < CAND_MAX) cand_idx[p] = 2 * i + 1;
                }
            }
            __syncthreads();
            const int m = (s_nc < CAND_MAX) ? s_nc : CAND_MAX;
            const float tv = val16(thr);
            if (tid < m && tv > 0.f) {
                int mi = cand_idx[tid];
                int rank = 0;
                for (int u2 = 0; u2 < m; u2++)
                    if (cand_idx[u2] < mi) rank++;
                if (rank < need) {
                    int p = atomicAdd(&s_pos, 1);
                    if (p < KAUX) {
                        g_ax_idx[r * KAUX + p] = mi;
                        g_ax_val[r * KAUX + p] = tv;
                    }
                }
            }
        }
        __syncthreads();
        if (tid == 0) g_ax_cnt[r] = (s_pos < KAUX) ? s_pos : KAUX;
    }
}

// ---------------- decode main: recon + mse partial ---------------------------
__global__ __launch_bounds__(256)
void decode_main_kernel(const float* __restrict__ x,
                        const float* __restrict__ bd, float* __restrict__ recon) {
    const int r = blockIdx.x, tid = threadIdx.x;
    __shared__ int   sidx_[TOPK];
    __shared__ float sval[TOPK];
    __shared__ double sred[256];

    const int cnt = g_tk_cnt[r];
    if (tid < cnt) { sidx_[tid] = g_tk_idx[r * TOPK + tid]; sval[tid] = g_tk_val[r * TOPK + tid]; }
    __syncthreads();

    float2 acc[4];
#pragma unroll
    for (int q = 0; q < 4; q++)
        acc[q] = *(const float2*)(bd + (size_t)(tid + 256 * q) * 2);

    for (int t = 0; t < cnt; t++) {
        const uint32_t* wq = g_Wd16u + (size_t)sidx_[t] * (D_INV / 2);
        float v = sval[t];
#pragma unroll
        for (int q = 0; q < 4; q++) {
            float2 wf = uph(wq[tid + 256 * q]);
            acc[q].x += v * wf.x;
            acc[q].y += v * wf.y;
        }
    }

    double pm = 0.0;
#pragma unroll
    for (int q = 0; q < 4; q++) {
        float2 xr = *(const float2*)(x + (size_t)r * D_INV + (size_t)(tid + 256 * q) * 2);
        *(float2*)(recon + (size_t)r * D_INV + (size_t)(tid + 256 * q) * 2) = acc[q];
        float ex = acc[q].x - xr.x, ey = acc[q].y - xr.y;
        pm += (double)ex * ex + (double)ey * ey;
    }

    sred[tid] = pm; __syncthreads();
    for (int s = 128; s > 0; s >>= 1) { if (tid < s) sred[tid] += sred[tid + s]; __syncthreads(); }
    if (tid == 0) g_pmse[r] = sred[0];
}

// ---------------- decode aux: fp8 gather + aux partial ------------------------
__global__ __launch_bounds__(256)
void decode_aux_kernel(const float* __restrict__ x,
                       const float* __restrict__ bd, const float* __restrict__ recon) {
    const int r = blockIdx.x, tid = threadIdx.x;
    __shared__ int   sidx_[KAUX];
    __shared__ float sval[KAUX];
    __shared__ double sred[256];

    const int acnt = g_ax_cnt[r];
    if (tid < acnt) { sidx_[tid] = g_ax_idx[r * KAUX + tid]; sval[tid] = g_ax_val[r * KAUX + tid]; }
    __syncthreads();

    float2 aacc[4];
#pragma unroll
    for (int q = 0; q < 4; q++)
        aacc[q] = *(const float2*)(bd + (size_t)(tid + 256 * q) * 2);

    for (int t = 0; t < acnt; t++) {
        const unsigned short* wq = g_Wd8u + (size_t)sidx_[t] * (D_INV / 2);
        float vs = sval[t] * WD8_INV;
#pragma unroll
        for (int q = 0; q < 4; q++) {
            uint32_t h2;
            asm("cvt.rn.f16x2.e4m3x2 %0, %1;" : "=r"(h2) : "h"(wq[tid + 256 * q]));
            float2 wf = uph(h2);
            aacc[q].x += vs * wf.x;
            aacc[q].y += vs * wf.y;
        }
    }

    double pa = 0.0;
#pragma unroll
    for (int q = 0; q < 4; q++) {
        size_t o = (size_t)r * D_INV + (size_t)(tid + 256 * q) * 2;
        float2 xr = *(const float2*)(x + o);
        float2 rc = *(const float2*)(recon + o);
        float rx = xr.x - rc.x, ry = xr.y - rc.y;
        float ex = aacc[q].x - rx, ey = aacc[q].y - ry;
        pa += (double)ex * ex + (double)ey * ey;
    }

    sred[tid] = pa; __syncthreads();
    for (int s = 128; s > 0; s >>= 1) { if (tid < s) sred[tid] += sred[tid + s]; __syncthreads(); }
    if (tid == 0) g_paux[r] = sred[0];
}

__global__ void finalize_kernel(float* __restrict__ scal) {
    __shared__ double sm[256], sa[256];
    const int tid = threadIdx.x;
    double m = 0.0, a = 0.0;
    for (int i = tid; i < B_TOK; i += 256) { m += g_pmse[i]; a += g_paux[i]; }
    sm[tid] = m; sa[tid] = a; __syncthreads();
    for (int s = 128; s > 0; s >>= 1) {
        if (tid < s) { sm[tid] += sm[tid + s]; sa[tid] += sa[tid + s]; }
        __syncthreads();
    }
    if (tid == 0) {
        const double denom = (double)B_TOK * (double)D_INV;
        double mse = sm[0] / denom;
        double aux = sa[0] / denom;
        scal[0] = (float)(mse + aux);
        scal[1] = (float)mse;
        scal[2] = (float)aux;
    }
}

// ---------------- launch ----------------------------------------------------
extern "C" void kernel_launch(void* const* d_in, const int* in_sizes, int n_in,
                              void* d_out, int out_size) {
    const float*     x     = (const float*)d_in[0];
    const float*     We    = (const float*)d_in[1];
    const float*     be    = (const float*)d_in[2];
    const float*     Wd    = (const float*)d_in[3];
    const float*     bd    = (const float*)d_in[4];
    const long long* steps = (const long long*)d_in[5];

    float* out    = (float*)d_out;
    float* recon  = out;
    float* coeffs = out + (size_t)B_TOK * D_INV;
    float* scal   = coeffs + (size_t)B_TOK * NF;

    const size_t topk_smem = 2048 + 5 * 256 * 4 + 2048 + (size_t)NF * 2;
    cudaFuncSetAttribute(topk_kernel, cudaFuncAttributeMaxDynamicSharedMemorySize,
                         (int)topk_smem);
    cudaFuncSetAttribute(gemm_f16_kernel, cudaFuncAttributeMaxDynamicSharedMemorySize,
                         GEMM_SMEM);

    cudaStream_t side;
    cudaStreamCreateWithFlags(&side, cudaStreamNonBlocking);
    cudaEvent_t evFork, evJoin, evTk, evDm;
    cudaEventCreateWithFlags(&evFork, cudaEventDisableTiming);
    cudaEventCreateWithFlags(&evJoin, cudaEventDisableTiming);
    cudaEventCreateWithFlags(&evTk, cudaEventDisableTiming);
    cudaEventCreateWithFlags(&evDm, cudaEventDisableTiming);

    // fork: conv_wd + coeffs memset on side stream (overlap GEMM chain)
    cudaEventRecord(evFork, 0);
    cudaStreamWaitEvent(side, evFork, 0);
    conv_wd_kernel<<<((size_t)NF * D_INV / 4) / 256, 256, 0, side>>>(Wd);
    cudaMemsetAsync(coeffs, 0, (size_t)B_TOK * NF * sizeof(float), side);
    cudaEventRecord(evJoin, side);

    // main: conversions + GEMM
    conv_a_kernel<<<(B_TOK * D_INV / 4) / 256, 256>>>(x);
    conv_b_kernel<<<dim3(NF / 32, D_INV / 32), 256>>>(We);
    gemm_f16_kernel<<<dim3(B_TOK / TM, NF / TN), 256, GEMM_SMEM>>>(be);

    cudaStreamWaitEvent(0, evJoin, 0);

    // main top-32
    topk_kernel<<<B_TOK, 256, topk_smem>>>(TOPK, 0, coeffs, x, We, be);
    cudaEventRecord(evTk, 0);

    // side: decode_main (depends on topk_main + conv_wd, both satisfied)
    cudaStreamWaitEvent(side, evTk, 0);
    decode_main_kernel<<<B_TOK, 256, 0, side>>>(x, bd, recon);
    cudaEventRecord(evDm, side);

    // main: dead + aux top-256 (overlaps decode_main)
    dead_kernel<<<(NF + 255) / 256, 256>>>(steps);
    topk_kernel<<<B_TOK, 256, topk_smem>>>(KAUX, 1, nullptr, x, We, be);

    // join decode_main, then aux decode + finalize
    cudaStreamWaitEvent(0, evDm, 0);
    decode_aux_kernel<<<B_TOK, 256>>>(x, bd, recon);
    finalize_kernel<<<1, 256>>>(scal);
}